// round 11
// baseline (speedup 1.0000x reference)
#include <cuda_runtime.h>
#include <cuda_bf16.h>
#include <math.h>

#define Bb 16
#define Ss 1024
#define Dd 512
#define Hh 512
#define Uu 512
#define MR (Bb*Ss)        // 16384 rows
#define G4U (4*Uu)        // 2048

// ---------------- scratch (device globals; no allocations allowed) ----------
__device__ float d_q[MR*Hh];
__device__ float d_k[MR*Hh];
__device__ float d_v[MR*Hh];
__device__ float d_scores[(size_t)Bb*Ss*Ss];
__device__ float d_ctx[MR*Hh];
__device__ float d_proj[MR*Uu];
__device__ float d_y1[MR*Uu];
__device__ float d_xp[(size_t)MR*G4U];
__device__ float d_hs[MR*Uu];
__device__ float d_hbuf[2][Bb*Uu];
__device__ int   d_flags[128];

// ---------------- scoped acquire/release helpers (no CCTL.IVALL!) -----------
__device__ __forceinline__ void st_release_gpu(int* p, int v) {
    asm volatile("st.release.gpu.global.s32 [%0], %1;" :: "l"(p), "r"(v) : "memory");
}
__device__ __forceinline__ int ld_acquire_gpu(const int* p) {
    int v;
    asm volatile("ld.acquire.gpu.global.s32 %0, [%1];" : "=r"(v) : "l"(p) : "memory");
    return v;
}

// ---------------- tensor-core primitives ------------------------------------
__device__ __forceinline__ void mma16816(float* d, const unsigned* a,
                                         unsigned b0, unsigned b1) {
    asm volatile(
        "mma.sync.aligned.m16n8k16.row.col.f32.bf16.bf16.f32 "
        "{%0,%1,%2,%3}, {%4,%5,%6,%7}, {%8,%9}, {%0,%1,%2,%3};\n"
        : "+f"(d[0]), "+f"(d[1]), "+f"(d[2]), "+f"(d[3])
        : "r"(a[0]), "r"(a[1]), "r"(a[2]), "r"(a[3]), "r"(b0), "r"(b1));
}
__device__ __forceinline__ void ldsm4(unsigned* r, const void* p) {
    unsigned addr = (unsigned)__cvta_generic_to_shared(p);
    asm volatile("ldmatrix.sync.aligned.m8n8.x4.shared.b16 {%0,%1,%2,%3}, [%4];\n"
        : "=r"(r[0]), "=r"(r[1]), "=r"(r[2]), "=r"(r[3]) : "r"(addr));
}
__device__ __forceinline__ void ldsm4t(unsigned* r, const void* p) {
    unsigned addr = (unsigned)__cvta_generic_to_shared(p);
    asm volatile("ldmatrix.sync.aligned.m8n8.x4.trans.shared.b16 {%0,%1,%2,%3}, [%4];\n"
        : "=r"(r[0]), "=r"(r[1]), "=r"(r[2]), "=r"(r[3]) : "r"(addr));
}

// Truncation split of a float4 into packed hi (2x uint32) and lo (cvt.rn.bf16x2).
// hi = top 16 bits (exact residual captured in lo; dropped product term ~2^-16).
__device__ __forceinline__ void split4(const float4 v, uint2& hi, uint2& lo) {
    unsigned a = __float_as_uint(v.x), b = __float_as_uint(v.y),
             c = __float_as_uint(v.z), d = __float_as_uint(v.w);
    hi.x = __byte_perm(a, b, 0x7632);
    hi.y = __byte_perm(c, d, 0x7632);
    float lx = v.x - __uint_as_float(a & 0xFFFF0000u);
    float ly = v.y - __uint_as_float(b & 0xFFFF0000u);
    float lz = v.z - __uint_as_float(c & 0xFFFF0000u);
    float lw = v.w - __uint_as_float(d & 0xFFFF0000u);
    __nv_bfloat162 l0 = __floats2bfloat162_rn(lx, ly);
    __nv_bfloat162 l1 = __floats2bfloat162_rn(lz, lw);
    lo.x = *(unsigned*)&l0;
    lo.y = *(unsigned*)&l1;
}

// ---------------- bf16-split-3 GEMM: C = alpha*A*op(B) (+bias) --------------
// A [M,K] fp32 row-major. TB==0: B [K,N] (staged [k][n], ldsm.trans);
// TB==1: B [N,K] (staged [n][k], plain ldsm).
// fp32 = hi+lo bf16; 3 mma passes (hh, hl, lh) ~ fp32 accuracy.
// CTA 128x128, 8 warps, warp tile 64x32 via m16n8k16, 2-stage pipeline,
// 2 CTAs/SM.
#define HS 24                       // A k-stride (bf16)
#define BKS 136                     // TB==0 B n-stride (bf16): 272B = 16B mod 128B
#define HG_SMEM 49152

template<int TB>
__global__ __launch_bounds__(256, 2) void hgemm3(
    const float* __restrict__ Ag, const float* __restrict__ Bg,
    float* __restrict__ Cg, const float* __restrict__ bias,
    int M, int N, int K, long sA, long sB, long sC, float alpha)
{
    extern __shared__ __nv_bfloat16 hsm[];
    const int BSTG = (TB == 1) ? 3072 : 2176;   // per-stage B bf16
    __nv_bfloat16* As_hi = hsm;                 // [2][3072]
    __nv_bfloat16* As_lo = hsm + 6144;
    __nv_bfloat16* Bs_hi = hsm + 12288;         // [2][BSTG]
    __nv_bfloat16* Bs_lo = Bs_hi + 2 * BSTG;

    const float* A = Ag + (long)blockIdx.z * sA;
    const float* B = Bg + (long)blockIdx.z * sB;
    float*       C = Cg + (long)blockIdx.z * sC;

    const int tid = threadIdx.x, lane = tid & 31, warp = tid >> 5;
    const int m0 = blockIdx.y * 128, n0 = blockIdx.x * 128;
    const int wr0 = (warp >> 2) * 64, wc0 = (warp & 3) * 32;

    float acc[4][4][4] = {};

    const int rowA = tid >> 2, c4 = (tid & 3) * 4;
    const float* pA0 = A + (long)(m0 + rowA) * K + c4;
    const float* pA1 = pA0 + (long)64 * K;
    const float *pB0, *pB1;
    int kB = 0, n4B = 0;
    if (TB == 1) {
        pB0 = B + (long)(n0 + rowA) * K + c4;
        pB1 = pB0 + (long)64 * K;
    } else {
        kB = tid >> 5; n4B = (tid & 31) * 4;
        pB0 = B + (long)kB * N + n0 + n4B;
        pB1 = pB0 + (long)8 * N;
    }

    const int nsteps = K / 16;
    float4 ra0, ra1, rb0, rb1;

    ra0 = *(const float4*)(pA0);  ra1 = *(const float4*)(pA1);
    rb0 = *(const float4*)(pB0);  rb1 = *(const float4*)(pB1);

    // ---- store one stage (packed 64-bit smem stores) ----
    auto store_stage = [&](int so_a, int so_b) {
        uint2 hi, lo;
        __nv_bfloat16* ah = As_hi + so_a + rowA * HS + c4;
        __nv_bfloat16* al = As_lo + so_a + rowA * HS + c4;
        split4(ra0, hi, lo);
        *(uint2*)ah = hi;              *(uint2*)al = lo;
        split4(ra1, hi, lo);
        *(uint2*)(ah + 64 * HS) = hi;  *(uint2*)(al + 64 * HS) = lo;
        if (TB == 1) {
            __nv_bfloat16* bh = Bs_hi + so_b + rowA * HS + c4;
            __nv_bfloat16* bl = Bs_lo + so_b + rowA * HS + c4;
            split4(rb0, hi, lo);
            *(uint2*)bh = hi;              *(uint2*)bl = lo;
            split4(rb1, hi, lo);
            *(uint2*)(bh + 64 * HS) = hi;  *(uint2*)(bl + 64 * HS) = lo;
        } else {
            __nv_bfloat16* bh = Bs_hi + so_b + kB * BKS + n4B;
            __nv_bfloat16* bl = Bs_lo + so_b + kB * BKS + n4B;
            split4(rb0, hi, lo);
            *(uint2*)bh = hi;              *(uint2*)bl = lo;
            split4(rb1, hi, lo);
            *(uint2*)(bh + 8 * BKS) = hi;  *(uint2*)(bl + 8 * BKS) = lo;
        }
    };

    store_stage(0, 0);
    if (nsteps > 1) {
        ra0 = *(const float4*)(pA0 + 16); ra1 = *(const float4*)(pA1 + 16);
        if (TB == 1) { rb0 = *(const float4*)(pB0 + 16); rb1 = *(const float4*)(pB1 + 16); }
        else { rb0 = *(const float4*)(pB0 + (long)16 * N); rb1 = *(const float4*)(pB1 + (long)16 * N); }
    }
    __syncthreads();

    // A fragment address
    const int fr = lane & 15, fc = (lane & 16) >> 1;
    // TB==1 B fragment address ([n][k])
    const int fn = (lane & 7) + ((lane & 16) >> 1);
    const int fk = lane & 8;
    // TB==0 B fragment address ([k][n], trans)
    const int tkr = lane & 15;                 // k row
    const int tnc = (lane >> 4) * 8;           // n col half

    for (int st = 0; st < nsteps; st++) {
        const int cur = st & 1;
        const int coa = cur * 3072;
        const int cob = cur * BSTG;

        unsigned ah[4][4], al4[4][4], bh[2][4], bl[2][4];
#pragma unroll
        for (int tm = 0; tm < 4; tm++) {
            ldsm4(ah[tm],  As_hi + coa + (wr0 + tm * 16 + fr) * HS + fc);
            ldsm4(al4[tm], As_lo + coa + (wr0 + tm * 16 + fr) * HS + fc);
        }
#pragma unroll
        for (int p = 0; p < 2; p++) {
            if (TB == 1) {
                ldsm4(bh[p], Bs_hi + cob + (wc0 + p * 16 + fn) * HS + fk);
                ldsm4(bl[p], Bs_lo + cob + (wc0 + p * 16 + fn) * HS + fk);
            } else {
                ldsm4t(bh[p], Bs_hi + cob + tkr * BKS + wc0 + p * 16 + tnc);
                ldsm4t(bl[p], Bs_lo + cob + tkr * BKS + wc0 + p * 16 + tnc);
            }
        }
#pragma unroll
        for (int tm = 0; tm < 4; tm++)
#pragma unroll
            for (int tn = 0; tn < 4; tn++) {
                unsigned b0h = bh[tn >> 1][(tn & 1) * 2], b1h = bh[tn >> 1][(tn & 1) * 2 + 1];
                unsigned b0l = bl[tn >> 1][(tn & 1) * 2], b1l = bl[tn >> 1][(tn & 1) * 2 + 1];
                mma16816(acc[tm][tn], ah[tm],  b0h, b1h);
                mma16816(acc[tm][tn], ah[tm],  b0l, b1l);
                mma16816(acc[tm][tn], al4[tm], b0h, b1h);
            }

        if (st + 1 < nsteps) {
            store_stage((cur ^ 1) * 3072, (cur ^ 1) * BSTG);
            if (st + 2 < nsteps) {
                int k0 = (st + 2) * 16;
                ra0 = *(const float4*)(pA0 + k0); ra1 = *(const float4*)(pA1 + k0);
                if (TB == 1) { rb0 = *(const float4*)(pB0 + k0); rb1 = *(const float4*)(pB1 + k0); }
                else { rb0 = *(const float4*)(pB0 + (long)k0 * N); rb1 = *(const float4*)(pB1 + (long)k0 * N); }
            }
        }
        __syncthreads();
    }

    const int er = lane >> 2, ec = (lane & 3) * 2;
#pragma unroll
    for (int tm = 0; tm < 4; tm++)
#pragma unroll
        for (int tn = 0; tn < 4; tn++) {
            int row = m0 + wr0 + tm * 16 + er;
            int col = n0 + wc0 + tn * 8 + ec;
            float b0 = bias ? bias[col] : 0.f;
            float b1 = bias ? bias[col + 1] : 0.f;
            float2 v0 = { alpha * acc[tm][tn][0] + b0, alpha * acc[tm][tn][1] + b1 };
            float2 v1 = { alpha * acc[tm][tn][2] + b0, alpha * acc[tm][tn][3] + b1 };
            *(float2*)&C[(long)row * N + col] = v0;
            *(float2*)&C[(long)(row + 8) * N + col] = v1;
        }
}

// ---------------- softmax over rows of length 1024 ---------------------------
__global__ __launch_bounds__(256) void softmax_k(float* __restrict__ s)
{
    __shared__ float red[8];
    long row = blockIdx.x;
    float* p = s + row * 1024;
    int tid = threadIdx.x;
    float4 v = ((float4*)p)[tid];

    float m = fmaxf(fmaxf(v.x, v.y), fmaxf(v.z, v.w));
#pragma unroll
    for (int o = 16; o; o >>= 1) m = fmaxf(m, __shfl_xor_sync(~0u, m, o));
    if ((tid & 31) == 0) red[tid >> 5] = m;
    __syncthreads();
    m = red[0];
#pragma unroll
    for (int i = 1; i < 8; i++) m = fmaxf(m, red[i]);

    v.x = expf(v.x - m); v.y = expf(v.y - m);
    v.z = expf(v.z - m); v.w = expf(v.w - m);
    float su = v.x + v.y + v.z + v.w;
#pragma unroll
    for (int o = 16; o; o >>= 1) su += __shfl_xor_sync(~0u, su, o);
    __syncthreads();
    if ((tid & 31) == 0) red[tid >> 5] = su;
    __syncthreads();
    su = 0.f;
#pragma unroll
    for (int i = 0; i < 8; i++) su += red[i];
    float inv = 1.f / su;
    v.x *= inv; v.y *= inv; v.z *= inv; v.w *= inv;
    ((float4*)p)[tid] = v;
}

// ---------------- fused residual add + LayerNorm (row len 512) --------------
__global__ __launch_bounds__(128) void ln_add_k(
    const float* __restrict__ a, const float* __restrict__ b,
    const float* __restrict__ gamma, const float* __restrict__ beta,
    float* __restrict__ out)
{
    __shared__ float red[4];
    long row = blockIdx.x;
    int tid = threadIdx.x;
    float4 x = ((const float4*)(a + row * 512))[tid];
    float4 y = ((const float4*)(b + row * 512))[tid];
    x.x += y.x; x.y += y.y; x.z += y.z; x.w += y.w;

    float su = x.x + x.y + x.z + x.w;
#pragma unroll
    for (int o = 16; o; o >>= 1) su += __shfl_xor_sync(~0u, su, o);
    if ((tid & 31) == 0) red[tid >> 5] = su;
    __syncthreads();
    su = red[0] + red[1] + red[2] + red[3];
    float mu = su * (1.f / 512.f);

    float4 dx;
    dx.x = x.x - mu; dx.y = x.y - mu; dx.z = x.z - mu; dx.w = x.w - mu;
    float sq = dx.x * dx.x + dx.y * dx.y + dx.z * dx.z + dx.w * dx.w;
#pragma unroll
    for (int o = 16; o; o >>= 1) sq += __shfl_xor_sync(~0u, sq, o);
    __syncthreads();
    if ((tid & 31) == 0) red[tid >> 5] = sq;
    __syncthreads();
    sq = red[0] + red[1] + red[2] + red[3];
    float inv = rsqrtf(sq * (1.f / 512.f) + 1e-3f);

    float4 g = ((const float4*)gamma)[tid];
    float4 bt = ((const float4*)beta)[tid];
    float4 o4;
    o4.x = g.x * dx.x * inv + bt.x;
    o4.y = g.y * dx.y * inv + bt.y;
    o4.z = g.z * dx.z * inv + bt.z;
    o4.w = g.w * dx.w * inv + bt.w;
    ((float4*)(out + row * 512))[tid] = o4;
}

// ---------------- reset for persistent LSTM sync state ----------------------
__global__ void reset_k()
{
    int tid = threadIdx.x + blockIdx.x * blockDim.x;
    if (tid < Bb * Uu) { d_hbuf[0][tid] = 0.f; d_hbuf[1][tid] = 0.f; }
    if (tid < 128) d_flags[tid] = 0;
}

// ---------------- persistent LSTM scan --------------------------------------
// 128 CTAs x 256 threads. CTA owns 16 gate cols (4 u's), all 16 batches.
// R slice in REGISTERS (32 float4/thread, loaded once).
// h layout: row start S(b) = b*608 + (b>>2)*8, intra-row kk = k4*4 + (k4>>3)*4.
// z_part: [ks][b][col] with col-stride 18 -> conflict-free reads, <=2-way stores.
#define LSTM_NCTA 128
#define HPITCH 608
#define LSTM_DSMEM (16 * HPITCH * 4)    // 38912 B

__global__ __launch_bounds__(256) void lstm_k(
    const float* __restrict__ xp, const float* __restrict__ R,
    float* __restrict__ hs)
{
    extern __shared__ float h_s[];         // staggered rows, see above
    __shared__ float z_part[16][16][18];   // [ks][b][col(+pad)]
    __shared__ float z_s[16][16];          // [col][b]
    __shared__ float c_s[4][17];

    const int tid = threadIdx.x;
    const int cta = blockIdx.x;
    const int u0  = cta * 4;

    const int cq = tid & 3;          // gate index (cols cq*4..cq*4+3)
    const int bq = (tid >> 2) & 3;   // batches bq*4..bq*4+3
    const int ks = tid >> 4;         // 16 k-slices of 32

    // R slice -> registers: rr[k] = 4 consecutive cols (gate cq, du 0..3)
    float4 rr[32];
#pragma unroll
    for (int k = 0; k < 32; k++)
        rr[k] = *(const float4*)&R[(long)(ks * 32 + k) * 2048 + cq * 512 + u0];

    if (tid < 64) c_s[tid >> 4][tid & 15] = 0.f;

    // four h-row pointers for this thread's batches (bq*4 + 0..3)
    const float* hp0 = h_s + (bq * 4 + 0) * HPITCH + bq * 8 + ks * 36;
    const float* hp1 = hp0 + HPITCH;
    const float* hp2 = hp1 + HPITCH;
    const float* hp3 = hp2 + HPITCH;

    const int rc = tid >> 4;         // reducer col 0..15
    const int rb = tid & 15;         // reducer batch 0..15
    const float* xp_t = xp + (long)rb * Ss * 2048
                           + (rc >> 2) * 512 + u0 + (rc & 3);

    __syncthreads();

    for (int t = 0; t < 1024; t++) {
        float xv = __ldg(xp_t + (long)t * 2048);

        // ---- wait for step-(t-1) h writes ----
        if (t > 0) {
            if (tid < LSTM_NCTA) {
                while (ld_acquire_gpu(&d_flags[tid]) < t) { }
            }
            __syncthreads();
        }

        // ---- stage h_{t-1} into staggered smem ----
        {
            const float4* hg = (const float4*)(d_hbuf[(t + 1) & 1]);
#pragma unroll
            for (int j = 0; j < 8; j++) {
                int i = tid + j * 256;          // 0..2047 float4
                float4 v = __ldcg(hg + i);
                int b = i >> 7, k4f = i & 127;
                int off = b * HPITCH + (b >> 2) * 8 + k4f * 4 + (k4f >> 3) * 4;
                *(float4*)(h_s + off) = v;
            }
        }
        __syncthreads();

        // ---- dot: 4 cols x 4 batches x 32 k, R in registers ----
        {
            float acc[4][4] = {};
#pragma unroll
            for (int k4 = 0; k4 < 8; k4++) {
                float4 hb0 = *(const float4*)(hp0 + k4 * 4);
                float4 hb1 = *(const float4*)(hp1 + k4 * 4);
                float4 hb2 = *(const float4*)(hp2 + k4 * 4);
                float4 hb3 = *(const float4*)(hp3 + k4 * 4);
#pragma unroll
                for (int kk = 0; kk < 4; kk++) {
                    float4 rc4 = rr[k4 * 4 + kk];
                    float h0 = (kk == 0) ? hb0.x : (kk == 1) ? hb0.y : (kk == 2) ? hb0.z : hb0.w;
                    float h1 = (kk == 0) ? hb1.x : (kk == 1) ? hb1.y : (kk == 2) ? hb1.z : hb1.w;
                    float h2 = (kk == 0) ? hb2.x : (kk == 1) ? hb2.y : (kk == 2) ? hb2.z : hb2.w;
                    float h3 = (kk == 0) ? hb3.x : (kk == 1) ? hb3.y : (kk == 2) ? hb3.z : hb3.w;
                    acc[0][0] += rc4.x * h0; acc[0][1] += rc4.x * h1;
                    acc[0][2] += rc4.x * h2; acc[0][3] += rc4.x * h3;
                    acc[1][0] += rc4.y * h0; acc[1][1] += rc4.y * h1;
                    acc[1][2] += rc4.y * h2; acc[1][3] += rc4.y * h3;
                    acc[2][0] += rc4.z * h0; acc[2][1] += rc4.z * h1;
                    acc[2][2] += rc4.z * h2; acc[2][3] += rc4.z * h3;
                    acc[3][0] += rc4.w * h0; acc[3][1] += rc4.w * h1;
                    acc[3][2] += rc4.w * h2; acc[3][3] += rc4.w * h3;
                }
            }
#pragma unroll
            for (int j = 0; j < 4; j++)
#pragma unroll
                for (int i = 0; i < 4; i++)
                    z_part[ks][bq * 4 + i][cq * 4 + j] = acc[j][i];
        }
        __syncthreads();

        // ---- reduce 16 k-slices + xp ----
        {
            float z = xv;
#pragma unroll
            for (int s = 0; s < 16; s++) z += z_part[s][rb][rc];
            z_s[rc][rb] = z;
        }
        __syncthreads();

        // ---- gate math: 64 threads, one (u, b) each ----
        if (tid < 64) {
            int du = tid >> 4, b = tid & 15;
            float zi = z_s[0 * 4 + du][b], zf = z_s[1 * 4 + du][b];
            float zg = z_s[2 * 4 + du][b], zo = z_s[3 * 4 + du][b];
            float si = 1.f / (1.f + expf(-zi));
            float sf = 1.f / (1.f + expf(-zf));
            float so = 1.f / (1.f + expf(-zo));
            float c  = sf * c_s[du][b] + si * fmaxf(zg, 0.f);
            c_s[du][b] = c;
            float h = so * fmaxf(c, 0.f);
            d_hbuf[t & 1][b * 512 + u0 + du] = h;
            hs[((long)b * Ss + t) * 512 + u0 + du] = h;
        }
        __syncthreads();

        // ---- signal step t done ----
        if (tid == 0) {
            st_release_gpu(&d_flags[cta], t + 1);
        }
    }
}

// ---------------- launch ------------------------------------------------------
extern "C" void kernel_launch(void* const* d_in, const int* in_sizes, int n_in,
                              void* d_out, int out_size)
{
    const float* emb   = (const float*)d_in[0];
    const float* Wq    = (const float*)d_in[1];
    const float* Wk    = (const float*)d_in[2];
    const float* Wv    = (const float*)d_in[3];
    const float* Wo    = (const float*)d_in[4];
    const float* gamma = (const float*)d_in[5];
    const float* beta  = (const float*)d_in[6];
    const float* lk    = (const float*)d_in[7];
    const float* lrk   = (const float*)d_in[8];
    const float* lb    = (const float*)d_in[9];

    float *q, *k, *v, *sc, *ctx, *proj, *y1, *xp, *hs;
    cudaGetSymbolAddress((void**)&q,    d_q);
    cudaGetSymbolAddress((void**)&k,    d_k);
    cudaGetSymbolAddress((void**)&v,    d_v);
    cudaGetSymbolAddress((void**)&sc,   d_scores);
    cudaGetSymbolAddress((void**)&ctx,  d_ctx);
    cudaGetSymbolAddress((void**)&proj, d_proj);
    cudaGetSymbolAddress((void**)&y1,   d_y1);
    cudaGetSymbolAddress((void**)&xp,   d_xp);
    cudaGetSymbolAddress((void**)&hs,   d_hs);

    cudaFuncSetAttribute(hgemm3<0>, cudaFuncAttributeMaxDynamicSharedMemorySize, HG_SMEM);
    cudaFuncSetAttribute(hgemm3<1>, cudaFuncAttributeMaxDynamicSharedMemorySize, HG_SMEM);

    const float sc_alpha = 0.044194173824159216f; // 1/sqrt(512)

    // reset LSTM sync state early (overlaps with GEMM chain)
    reset_k<<<32, 256>>>();

    // Q, K, V
    hgemm3<0><<<dim3(4, 128, 1), 256, HG_SMEM>>>(emb, Wq, q, nullptr, MR, Hh, Dd, 0, 0, 0, 1.f);
    hgemm3<0><<<dim3(4, 128, 1), 256, HG_SMEM>>>(emb, Wk, k, nullptr, MR, Hh, Dd, 0, 0, 0, 1.f);
    hgemm3<0><<<dim3(4, 128, 1), 256, HG_SMEM>>>(emb, Wv, v, nullptr, MR, Hh, Dd, 0, 0, 0, 1.f);

    // scores = Q K^T / sqrt(H)   (batched NT)
    hgemm3<1><<<dim3(8, 8, 16), 256, HG_SMEM>>>(q, k, sc, nullptr, Ss, Ss, Hh,
                                      (long)Ss * Hh, (long)Ss * Hh, (long)Ss * Ss, sc_alpha);
    softmax_k<<<Bb * Ss, 256>>>(sc);

    // ctx = attn V   (batched NN)
    hgemm3<0><<<dim3(4, 8, 16), 256, HG_SMEM>>>(sc, v, ctx, nullptr, Ss, Hh, Ss,
                                      (long)Ss * Ss, (long)Ss * Hh, (long)Ss * Hh, 1.f);

    // out-proj + residual LN
    hgemm3<0><<<dim3(4, 128, 1), 256, HG_SMEM>>>(ctx, Wo, proj, nullptr, MR, Uu, Hh, 0, 0, 0, 1.f);
    ln_add_k<<<MR, 128>>>(proj, emb, gamma, beta, y1);

    // LSTM input projection (+bias)
    hgemm3<0><<<dim3(16, 128, 1), 256, HG_SMEM>>>(y1, lk, xp, lb, MR, G4U, Uu, 0, 0, 0, 1.f);

    // persistent LSTM scan
    cudaFuncSetAttribute(lstm_k, cudaFuncAttributeMaxDynamicSharedMemorySize, LSTM_DSMEM);
    lstm_k<<<LSTM_NCTA, 256, LSTM_DSMEM>>>(xp, lrk, hs);

    // final residual LN -> output
    ln_add_k<<<MR, 128>>>(hs, y1, gamma, beta, (float*)d_out);
}

// round 12
// speedup vs baseline: 1.1423x; 1.1423x over previous
#include <cuda_runtime.h>
#include <cuda_bf16.h>
#include <math.h>

#define Bb 16
#define Ss 1024
#define Dd 512
#define Hh 512
#define Uu 512
#define MR (Bb*Ss)        // 16384 rows
#define G4U (4*Uu)        // 2048

// ---------------- scratch (device globals; no allocations allowed) ----------
__device__ float d_q[MR*Hh];
__device__ float d_k[MR*Hh];
__device__ float d_v[MR*Hh];
__device__ float d_scores[(size_t)Bb*Ss*Ss];
__device__ float d_ctx[MR*Hh];
__device__ float d_proj[MR*Uu];
__device__ float d_y1[MR*Uu];
__device__ float d_xp[(size_t)MR*G4U];
__device__ float d_hs[MR*Uu];
__device__ float d_hbuf[2][Bb*Uu];
__device__ int   d_flags[128];

// ---------------- scoped acquire/release helpers (no CCTL.IVALL!) -----------
__device__ __forceinline__ void st_release_gpu(int* p, int v) {
    asm volatile("st.release.gpu.global.s32 [%0], %1;" :: "l"(p), "r"(v) : "memory");
}
__device__ __forceinline__ int ld_acquire_gpu(const int* p) {
    int v;
    asm volatile("ld.acquire.gpu.global.s32 %0, [%1];" : "=r"(v) : "l"(p) : "memory");
    return v;
}

// ---------------- tensor-core primitives ------------------------------------
__device__ __forceinline__ void mma16816(float* d, const unsigned* a,
                                         unsigned b0, unsigned b1) {
    asm volatile(
        "mma.sync.aligned.m16n8k16.row.col.f32.bf16.bf16.f32 "
        "{%0,%1,%2,%3}, {%4,%5,%6,%7}, {%8,%9}, {%0,%1,%2,%3};\n"
        : "+f"(d[0]), "+f"(d[1]), "+f"(d[2]), "+f"(d[3])
        : "r"(a[0]), "r"(a[1]), "r"(a[2]), "r"(a[3]), "r"(b0), "r"(b1));
}
__device__ __forceinline__ void ldsm4(unsigned* r, const void* p) {
    unsigned addr = (unsigned)__cvta_generic_to_shared(p);
    asm volatile("ldmatrix.sync.aligned.m8n8.x4.shared.b16 {%0,%1,%2,%3}, [%4];\n"
        : "=r"(r[0]), "=r"(r[1]), "=r"(r[2]), "=r"(r[3]) : "r"(addr));
}
__device__ __forceinline__ void ldsm4t(unsigned* r, const void* p) {
    unsigned addr = (unsigned)__cvta_generic_to_shared(p);
    asm volatile("ldmatrix.sync.aligned.m8n8.x4.trans.shared.b16 {%0,%1,%2,%3}, [%4];\n"
        : "=r"(r[0]), "=r"(r[1]), "=r"(r[2]), "=r"(r[3]) : "r"(addr));
}

// Truncation split of a float4 into packed hi (2x uint32) and lo (cvt.rn.bf16x2).
__device__ __forceinline__ void split4(const float4 v, uint2& hi, uint2& lo) {
    unsigned a = __float_as_uint(v.x), b = __float_as_uint(v.y),
             c = __float_as_uint(v.z), d = __float_as_uint(v.w);
    hi.x = __byte_perm(a, b, 0x7632);
    hi.y = __byte_perm(c, d, 0x7632);
    float lx = v.x - __uint_as_float(a & 0xFFFF0000u);
    float ly = v.y - __uint_as_float(b & 0xFFFF0000u);
    float lz = v.z - __uint_as_float(c & 0xFFFF0000u);
    float lw = v.w - __uint_as_float(d & 0xFFFF0000u);
    __nv_bfloat162 l0 = __floats2bfloat162_rn(lx, ly);
    __nv_bfloat162 l1 = __floats2bfloat162_rn(lz, lw);
    lo.x = *(unsigned*)&l0;
    lo.y = *(unsigned*)&l1;
}
// scalar split
__device__ __forceinline__ void split1(float v, __nv_bfloat16* hi, __nv_bfloat16* lo) {
    unsigned u = __float_as_uint(v);
    unsigned short hb = (unsigned short)(u >> 16);
    *(unsigned short*)hi = hb;
    float l = v - __uint_as_float(u & 0xFFFF0000u);
    *lo = __float2bfloat16(l);
}

// ---------------- bf16-split-3 GEMM: C = alpha*A*op(B) (+bias) --------------
#define HS 24                       // A k-stride (bf16)
#define BKS 136                     // TB==0 B n-stride (bf16)
#define HG_SMEM 49152

template<int TB>
__global__ __launch_bounds__(256, 2) void hgemm3(
    const float* __restrict__ Ag, const float* __restrict__ Bg,
    float* __restrict__ Cg, const float* __restrict__ bias,
    int M, int N, int K, long sA, long sB, long sC, float alpha)
{
    extern __shared__ __nv_bfloat16 hsm[];
    const int BSTG = (TB == 1) ? 3072 : 2176;
    __nv_bfloat16* As_hi = hsm;
    __nv_bfloat16* As_lo = hsm + 6144;
    __nv_bfloat16* Bs_hi = hsm + 12288;
    __nv_bfloat16* Bs_lo = Bs_hi + 2 * BSTG;

    const float* A = Ag + (long)blockIdx.z * sA;
    const float* B = Bg + (long)blockIdx.z * sB;
    float*       C = Cg + (long)blockIdx.z * sC;

    const int tid = threadIdx.x, lane = tid & 31, warp = tid >> 5;
    const int m0 = blockIdx.y * 128, n0 = blockIdx.x * 128;
    const int wr0 = (warp >> 2) * 64, wc0 = (warp & 3) * 32;

    float acc[4][4][4] = {};

    const int rowA = tid >> 2, c4 = (tid & 3) * 4;
    const float* pA0 = A + (long)(m0 + rowA) * K + c4;
    const float* pA1 = pA0 + (long)64 * K;
    const float *pB0, *pB1;
    int kB = 0, n4B = 0;
    if (TB == 1) {
        pB0 = B + (long)(n0 + rowA) * K + c4;
        pB1 = pB0 + (long)64 * K;
    } else {
        kB = tid >> 5; n4B = (tid & 31) * 4;
        pB0 = B + (long)kB * N + n0 + n4B;
        pB1 = pB0 + (long)8 * N;
    }

    const int nsteps = K / 16;
    float4 ra0, ra1, rb0, rb1;

    ra0 = *(const float4*)(pA0);  ra1 = *(const float4*)(pA1);
    rb0 = *(const float4*)(pB0);  rb1 = *(const float4*)(pB1);

    auto store_stage = [&](int so_a, int so_b) {
        uint2 hi, lo;
        __nv_bfloat16* ah = As_hi + so_a + rowA * HS + c4;
        __nv_bfloat16* al = As_lo + so_a + rowA * HS + c4;
        split4(ra0, hi, lo);
        *(uint2*)ah = hi;              *(uint2*)al = lo;
        split4(ra1, hi, lo);
        *(uint2*)(ah + 64 * HS) = hi;  *(uint2*)(al + 64 * HS) = lo;
        if (TB == 1) {
            __nv_bfloat16* bh = Bs_hi + so_b + rowA * HS + c4;
            __nv_bfloat16* bl = Bs_lo + so_b + rowA * HS + c4;
            split4(rb0, hi, lo);
            *(uint2*)bh = hi;              *(uint2*)bl = lo;
            split4(rb1, hi, lo);
            *(uint2*)(bh + 64 * HS) = hi;  *(uint2*)(bl + 64 * HS) = lo;
        } else {
            __nv_bfloat16* bh = Bs_hi + so_b + kB * BKS + n4B;
            __nv_bfloat16* bl = Bs_lo + so_b + kB * BKS + n4B;
            split4(rb0, hi, lo);
            *(uint2*)bh = hi;              *(uint2*)bl = lo;
            split4(rb1, hi, lo);
            *(uint2*)(bh + 8 * BKS) = hi;  *(uint2*)(bl + 8 * BKS) = lo;
        }
    };

    store_stage(0, 0);
    if (nsteps > 1) {
        ra0 = *(const float4*)(pA0 + 16); ra1 = *(const float4*)(pA1 + 16);
        if (TB == 1) { rb0 = *(const float4*)(pB0 + 16); rb1 = *(const float4*)(pB1 + 16); }
        else { rb0 = *(const float4*)(pB0 + (long)16 * N); rb1 = *(const float4*)(pB1 + (long)16 * N); }
    }
    __syncthreads();

    const int fr = lane & 15, fc = (lane & 16) >> 1;
    const int fn = (lane & 7) + ((lane & 16) >> 1);
    const int fk = lane & 8;
    const int tkr = lane & 15;
    const int tnc = (lane >> 4) * 8;

    for (int st = 0; st < nsteps; st++) {
        const int cur = st & 1;
        const int coa = cur * 3072;
        const int cob = cur * BSTG;

        unsigned ah[4][4], al4[4][4], bh[2][4], bl[2][4];
#pragma unroll
        for (int tm = 0; tm < 4; tm++) {
            ldsm4(ah[tm],  As_hi + coa + (wr0 + tm * 16 + fr) * HS + fc);
            ldsm4(al4[tm], As_lo + coa + (wr0 + tm * 16 + fr) * HS + fc);
        }
#pragma unroll
        for (int p = 0; p < 2; p++) {
            if (TB == 1) {
                ldsm4(bh[p], Bs_hi + cob + (wc0 + p * 16 + fn) * HS + fk);
                ldsm4(bl[p], Bs_lo + cob + (wc0 + p * 16 + fn) * HS + fk);
            } else {
                ldsm4t(bh[p], Bs_hi + cob + tkr * BKS + wc0 + p * 16 + tnc);
                ldsm4t(bl[p], Bs_lo + cob + tkr * BKS + wc0 + p * 16 + tnc);
            }
        }
#pragma unroll
        for (int tm = 0; tm < 4; tm++)
#pragma unroll
            for (int tn = 0; tn < 4; tn++) {
                unsigned b0h = bh[tn >> 1][(tn & 1) * 2], b1h = bh[tn >> 1][(tn & 1) * 2 + 1];
                unsigned b0l = bl[tn >> 1][(tn & 1) * 2], b1l = bl[tn >> 1][(tn & 1) * 2 + 1];
                mma16816(acc[tm][tn], ah[tm],  b0h, b1h);
                mma16816(acc[tm][tn], ah[tm],  b0l, b1l);
                mma16816(acc[tm][tn], al4[tm], b0h, b1h);
            }

        if (st + 1 < nsteps) {
            store_stage((cur ^ 1) * 3072, (cur ^ 1) * BSTG);
            if (st + 2 < nsteps) {
                int k0 = (st + 2) * 16;
                ra0 = *(const float4*)(pA0 + k0); ra1 = *(const float4*)(pA1 + k0);
                if (TB == 1) { rb0 = *(const float4*)(pB0 + k0); rb1 = *(const float4*)(pB1 + k0); }
                else { rb0 = *(const float4*)(pB0 + (long)k0 * N); rb1 = *(const float4*)(pB1 + (long)k0 * N); }
            }
        }
        __syncthreads();
    }

    const int er = lane >> 2, ec = (lane & 3) * 2;
#pragma unroll
    for (int tm = 0; tm < 4; tm++)
#pragma unroll
        for (int tn = 0; tn < 4; tn++) {
            int row = m0 + wr0 + tm * 16 + er;
            int col = n0 + wc0 + tn * 8 + ec;
            float b0 = bias ? bias[col] : 0.f;
            float b1 = bias ? bias[col + 1] : 0.f;
            float2 v0 = { alpha * acc[tm][tn][0] + b0, alpha * acc[tm][tn][1] + b1 };
            float2 v1 = { alpha * acc[tm][tn][2] + b0, alpha * acc[tm][tn][3] + b1 };
            *(float2*)&C[(long)row * N + col] = v0;
            *(float2*)&C[(long)(row + 8) * N + col] = v1;
        }
}

// ---------------- softmax over rows of length 1024 ---------------------------
__global__ __launch_bounds__(256) void softmax_k(float* __restrict__ s)
{
    __shared__ float red[8];
    long row = blockIdx.x;
    float* p = s + row * 1024;
    int tid = threadIdx.x;
    float4 v = ((float4*)p)[tid];

    float m = fmaxf(fmaxf(v.x, v.y), fmaxf(v.z, v.w));
#pragma unroll
    for (int o = 16; o; o >>= 1) m = fmaxf(m, __shfl_xor_sync(~0u, m, o));
    if ((tid & 31) == 0) red[tid >> 5] = m;
    __syncthreads();
    m = red[0];
#pragma unroll
    for (int i = 1; i < 8; i++) m = fmaxf(m, red[i]);

    v.x = expf(v.x - m); v.y = expf(v.y - m);
    v.z = expf(v.z - m); v.w = expf(v.w - m);
    float su = v.x + v.y + v.z + v.w;
#pragma unroll
    for (int o = 16; o; o >>= 1) su += __shfl_xor_sync(~0u, su, o);
    __syncthreads();
    if ((tid & 31) == 0) red[tid >> 5] = su;
    __syncthreads();
    su = 0.f;
#pragma unroll
    for (int i = 0; i < 8; i++) su += red[i];
    float inv = 1.f / su;
    v.x *= inv; v.y *= inv; v.z *= inv; v.w *= inv;
    ((float4*)p)[tid] = v;
}

// ---------------- fused residual add + LayerNorm (row len 512) --------------
__global__ __launch_bounds__(128) void ln_add_k(
    const float* __restrict__ a, const float* __restrict__ b,
    const float* __restrict__ gamma, const float* __restrict__ beta,
    float* __restrict__ out)
{
    __shared__ float red[4];
    long row = blockIdx.x;
    int tid = threadIdx.x;
    float4 x = ((const float4*)(a + row * 512))[tid];
    float4 y = ((const float4*)(b + row * 512))[tid];
    x.x += y.x; x.y += y.y; x.z += y.z; x.w += y.w;

    float su = x.x + x.y + x.z + x.w;
#pragma unroll
    for (int o = 16; o; o >>= 1) su += __shfl_xor_sync(~0u, su, o);
    if ((tid & 31) == 0) red[tid >> 5] = su;
    __syncthreads();
    su = red[0] + red[1] + red[2] + red[3];
    float mu = su * (1.f / 512.f);

    float4 dx;
    dx.x = x.x - mu; dx.y = x.y - mu; dx.z = x.z - mu; dx.w = x.w - mu;
    float sq = dx.x * dx.x + dx.y * dx.y + dx.z * dx.z + dx.w * dx.w;
#pragma unroll
    for (int o = 16; o; o >>= 1) sq += __shfl_xor_sync(~0u, sq, o);
    __syncthreads();
    if ((tid & 31) == 0) red[tid >> 5] = sq;
    __syncthreads();
    sq = red[0] + red[1] + red[2] + red[3];
    float inv = rsqrtf(sq * (1.f / 512.f) + 1e-3f);

    float4 g = ((const float4*)gamma)[tid];
    float4 bt = ((const float4*)beta)[tid];
    float4 o4;
    o4.x = g.x * dx.x * inv + bt.x;
    o4.y = g.y * dx.y * inv + bt.y;
    o4.z = g.z * dx.z * inv + bt.z;
    o4.w = g.w * dx.w * inv + bt.w;
    ((float4*)(out + row * 512))[tid] = o4;
}

// ---------------- reset for persistent LSTM sync state ----------------------
__global__ void reset_k()
{
    int tid = threadIdx.x + blockIdx.x * blockDim.x;
    if (tid < Bb * Uu) { d_hbuf[0][tid] = 0.f; d_hbuf[1][tid] = 0.f; }
    if (tid < 128) d_flags[tid] = 0;
}

// ---------------- persistent LSTM scan (tensor-core recurrence) -------------
// 128 CTAs x 256 threads. CTA owns 16 gate cols (4 u's), all 16 batches.
// z[16b][16col] = h[16b][512k] . R^T[16col][512k] via mma.m16n8k16 split-3.
// R^T staged once as bf16 hi/lo [col][k]; each warp owns a 64-k slice and
// keeps its B fragments (hi+lo, 32 regs) for the whole scan.
// h staged per step as bf16 hi/lo [b][k] (split during gmem->smem copy).
// Fragment mappings copied verbatim from hgemm3 (verified).
#define LSTM_NCTA 128
#define HB 520                       // bf16 row pitch (1040 B)
#define LSTM_DSMEM (4 * 16 * HB * 2) // h_hi,h_lo,r_hi,r_lo = 66560 B

__global__ __launch_bounds__(256) void lstm_k(
    const float* __restrict__ xp, const float* __restrict__ R,
    float* __restrict__ hs)
{
    extern __shared__ __nv_bfloat16 bsm[];
    __nv_bfloat16* h_hi = bsm;               // [16 b][HB]
    __nv_bfloat16* h_lo = bsm + 16 * HB;
    __nv_bfloat16* r_hi = bsm + 32 * HB;     // [16 col][HB]
    __nv_bfloat16* r_lo = bsm + 48 * HB;
    __shared__ float z_part[8][16][18];      // [warp][b][col(+pad)]
    __shared__ float z_s[16][16];            // [col][b]
    __shared__ float c_s[4][17];

    const int tid  = threadIdx.x;
    const int lane = tid & 31;
    const int w    = tid >> 5;               // 8 warps, k-slice w*64
    const int cta  = blockIdx.x;
    const int u0   = cta * 4;

    // ---- stage R^T split once: r[col][k], col c -> R[k][(c>>2)*512+u0+(c&3)]
    for (int idx = tid; idx < 8192; idx += 256) {
        int c = idx & 15, k = idx >> 4;
        float v = R[(long)k * 2048 + (c >> 2) * 512 + u0 + (c & 3)];
        split1(v, r_hi + c * HB + k, r_lo + c * HB + k);
    }
    if (tid < 64) c_s[tid >> 4][tid & 15] = 0.f;
    __syncthreads();

    // ---- persistent B fragments (R) ----
    const int fn = (lane & 7) + ((lane & 16) >> 1);   // col row
    const int fk = lane & 8;                          // k half
    unsigned rbh[4][4], rbl[4][4];
#pragma unroll
    for (int q = 0; q < 4; q++) {
        ldsm4(rbh[q], r_hi + fn * HB + w * 64 + q * 16 + fk);
        ldsm4(rbl[q], r_lo + fn * HB + w * 64 + q * 16 + fk);
    }

    const int fr = lane & 15, fcA = (lane & 16) >> 1; // A-frag addr
    const int er = lane >> 2, ec = (lane & 3) * 2;    // C-frag mapping

    const int rc = tid >> 4;         // reducer col 0..15
    const int rb = tid & 15;         // reducer batch 0..15
    const float* xp_t = xp + (long)rb * Ss * 2048
                           + (rc >> 2) * 512 + u0 + (rc & 3);

    __syncthreads();

    for (int t = 0; t < 1024; t++) {
        float xv = __ldg(xp_t + (long)t * 2048);

        // ---- wait for step-(t-1) h writes ----
        if (t > 0) {
            if (tid < LSTM_NCTA) {
                while (ld_acquire_gpu(&d_flags[tid]) < t) { }
            }
            __syncthreads();
        }

        // ---- stage h_{t-1}: fp32 gmem -> split bf16 hi/lo smem [b][k] ----
        {
            const float4* hg = (const float4*)(d_hbuf[(t + 1) & 1]);
#pragma unroll
            for (int j = 0; j < 8; j++) {
                int i = tid + j * 256;          // 0..2047 float4
                float4 v = __ldcg(hg + i);
                int b = i >> 7, k = (i & 127) * 4;
                uint2 hi, lo;
                split4(v, hi, lo);
                *(uint2*)(h_hi + b * HB + k) = hi;
                *(uint2*)(h_lo + b * HB + k) = lo;
            }
        }
        __syncthreads();

        // ---- tensor-core dot: warp w does k-slice [w*64, w*64+64) ----
        {
            float acc0[4] = {}, acc1[4] = {};
#pragma unroll
            for (int q = 0; q < 4; q++) {
                unsigned ahh[4], ahl[4];
                ldsm4(ahh, h_hi + fr * HB + w * 64 + q * 16 + fcA);
                ldsm4(ahl, h_lo + fr * HB + w * 64 + q * 16 + fcA);
                mma16816(acc0, ahh, rbh[q][0], rbh[q][1]);
                mma16816(acc1, ahh, rbh[q][2], rbh[q][3]);
                mma16816(acc0, ahh, rbl[q][0], rbl[q][1]);
                mma16816(acc1, ahh, rbl[q][2], rbl[q][3]);
                mma16816(acc0, ahl, rbh[q][0], rbh[q][1]);
                mma16816(acc1, ahl, rbh[q][2], rbh[q][3]);
            }
            // C-frag: rows er, er+8 (batch); cols ec,ec+1 (+8 for acc1)
            z_part[w][er][ec]         = acc0[0];
            z_part[w][er][ec + 1]     = acc0[1];
            z_part[w][er + 8][ec]     = acc0[2];
            z_part[w][er + 8][ec + 1] = acc0[3];
            z_part[w][er][ec + 8]     = acc1[0];
            z_part[w][er][ec + 9]     = acc1[1];
            z_part[w][er + 8][ec + 8] = acc1[2];
            z_part[w][er + 8][ec + 9] = acc1[3];
        }
        __syncthreads();

        // ---- reduce 8 warp-slices + xp ----
        {
            float z = xv;
#pragma unroll
            for (int s = 0; s < 8; s++) z += z_part[s][rb][rc];
            z_s[rc][rb] = z;
        }
        __syncthreads();

        // ---- gate math: 64 threads, one (u, b) each ----
        if (tid < 64) {
            int du = tid >> 4, b = tid & 15;
            float zi = z_s[0 * 4 + du][b], zf = z_s[1 * 4 + du][b];
            float zg = z_s[2 * 4 + du][b], zo = z_s[3 * 4 + du][b];
            float si = 1.f / (1.f + expf(-zi));
            float sf = 1.f / (1.f + expf(-zf));
            float so = 1.f / (1.f + expf(-zo));
            float c  = sf * c_s[du][b] + si * fmaxf(zg, 0.f);
            c_s[du][b] = c;
            float h = so * fmaxf(c, 0.f);
            d_hbuf[t & 1][b * 512 + u0 + du] = h;
            hs[((long)b * Ss + t) * 512 + u0 + du] = h;
        }
        __syncthreads();

        // ---- signal step t done ----
        if (tid == 0) {
            st_release_gpu(&d_flags[cta], t + 1);
        }
    }
}

// ---------------- launch ------------------------------------------------------
extern "C" void kernel_launch(void* const* d_in, const int* in_sizes, int n_in,
                              void* d_out, int out_size)
{
    const float* emb   = (const float*)d_in[0];
    const float* Wq    = (const float*)d_in[1];
    const float* Wk    = (const float*)d_in[2];
    const float* Wv    = (const float*)d_in[3];
    const float* Wo    = (const float*)d_in[4];
    const float* gamma = (const float*)d_in[5];
    const float* beta  = (const float*)d_in[6];
    const float* lk    = (const float*)d_in[7];
    const float* lrk   = (const float*)d_in[8];
    const float* lb    = (const float*)d_in[9];

    float *q, *k, *v, *sc, *ctx, *proj, *y1, *xp, *hs;
    cudaGetSymbolAddress((void**)&q,    d_q);
    cudaGetSymbolAddress((void**)&k,    d_k);
    cudaGetSymbolAddress((void**)&v,    d_v);
    cudaGetSymbolAddress((void**)&sc,   d_scores);
    cudaGetSymbolAddress((void**)&ctx,  d_ctx);
    cudaGetSymbolAddress((void**)&proj, d_proj);
    cudaGetSymbolAddress((void**)&y1,   d_y1);
    cudaGetSymbolAddress((void**)&xp,   d_xp);
    cudaGetSymbolAddress((void**)&hs,   d_hs);

    cudaFuncSetAttribute(hgemm3<0>, cudaFuncAttributeMaxDynamicSharedMemorySize, HG_SMEM);
    cudaFuncSetAttribute(hgemm3<1>, cudaFuncAttributeMaxDynamicSharedMemorySize, HG_SMEM);

    const float sc_alpha = 0.044194173824159216f; // 1/sqrt(512)

    // reset LSTM sync state early (overlaps with GEMM chain)
    reset_k<<<32, 256>>>();

    // Q, K, V
    hgemm3<0><<<dim3(4, 128, 1), 256, HG_SMEM>>>(emb, Wq, q, nullptr, MR, Hh, Dd, 0, 0, 0, 1.f);
    hgemm3<0><<<dim3(4, 128, 1), 256, HG_SMEM>>>(emb, Wk, k, nullptr, MR, Hh, Dd, 0, 0, 0, 1.f);
    hgemm3<0><<<dim3(4, 128, 1), 256, HG_SMEM>>>(emb, Wv, v, nullptr, MR, Hh, Dd, 0, 0, 0, 1.f);

    // scores = Q K^T / sqrt(H)   (batched NT)
    hgemm3<1><<<dim3(8, 8, 16), 256, HG_SMEM>>>(q, k, sc, nullptr, Ss, Ss, Hh,
                                      (long)Ss * Hh, (long)Ss * Hh, (long)Ss * Ss, sc_alpha);
    softmax_k<<<Bb * Ss, 256>>>(sc);

    // ctx = attn V   (batched NN)
    hgemm3<0><<<dim3(4, 8, 16), 256, HG_SMEM>>>(sc, v, ctx, nullptr, Ss, Hh, Ss,
                                      (long)Ss * Ss, (long)Ss * Hh, (long)Ss * Hh, 1.f);

    // out-proj + residual LN
    hgemm3<0><<<dim3(4, 128, 1), 256, HG_SMEM>>>(ctx, Wo, proj, nullptr, MR, Uu, Hh, 0, 0, 0, 1.f);
    ln_add_k<<<MR, 128>>>(proj, emb, gamma, beta, y1);

    // LSTM input projection (+bias)
    hgemm3<0><<<dim3(16, 128, 1), 256, HG_SMEM>>>(y1, lk, xp, lb, MR, G4U, Uu, 0, 0, 0, 1.f);

    // persistent LSTM scan
    cudaFuncSetAttribute(lstm_k, cudaFuncAttributeMaxDynamicSharedMemorySize, LSTM_DSMEM);
    lstm_k<<<LSTM_NCTA, 256, LSTM_DSMEM>>>(xp, lrk, hs);

    // final residual LN -> output
    ln_add_k<<<MR, 128>>>(hs, y1, gamma, beta, (float*)d_out);
}